// round 3
// baseline (speedup 1.0000x reference)
#include <cuda_runtime.h>
#include <math.h>

// Problem constants
#define BN 8
#define CN 256
#define ON 256
#define HN 64
#define WN 64
#define HW 4096          // HN*WN
#define K2 9
#define DGN 4
#define CGN 64           // CN/DGN
#define KD 2304          // CN*K2  (GEMM reduction dim)
#define GN_GROUPS 32
#define GRP_ELEMS 32768  // (ON/GN_GROUPS)*HW
#define EPS 1e-5f

// ---------------------------------------------------------------------------
// Scratch (static device globals: no runtime allocation allowed)
// ---------------------------------------------------------------------------
__device__ float g_col[(size_t)BN * KD * HW];   // 302 MB im2col buffer
__device__ float g_mu[BN * GN_GROUPS];
__device__ float g_rstd[BN * GN_GROUPS];

// ---------------------------------------------------------------------------
// Kernel 1: fused offset-projection + deformable im2col
// One thread per (b, g, k, hw). Bilinear params computed once, reused for all
// 64 channels of the deform group.
// col[b][(g*64+c)*9+k][hw] = bilinear_sample(x[b, g*64+c], h+ky+offy, w+kx+offx)
// ---------------------------------------------------------------------------
__global__ void im2col_kernel(const float* __restrict__ x,
                              const float* __restrict__ x_off,
                              const float* __restrict__ w_offset)
{
    int idx = blockIdx.x * blockDim.x + threadIdx.x;
    // total = BN*DGN*K2*HW = 1179648
    int hw = idx & (HW - 1);
    int t  = idx >> 12;          // b*36 + g*9 + k
    int k  = t % 9;
    int g  = (t / 9) & 3;
    int b  = t / 36;
    int h  = hw >> 6;
    int w  = hw & 63;

    // offset projection: offset channel oc = ((g*9 + k)*2 + {0=y,1=x})
    const float* xo = x_off + (size_t)b * 4 * HW + hw;
    float o0 = xo[0], o1 = xo[HW], o2 = xo[2 * HW], o3 = xo[3 * HW];
    const float* wo = w_offset + (size_t)((g * K2 + k) * 2) * 4;
    float offy = wo[0] * o0 + wo[1] * o1 + wo[2] * o2 + wo[3] * o3;
    float offx = wo[4] * o0 + wo[5] * o1 + wo[6] * o2 + wo[7] * o3;

    float py = (float)(h + k / 3 - 1) + offy;
    float px = (float)(w + k % 3 - 1) + offx;

    float fy = floorf(py), fx = floorf(px);
    int y0 = (int)fy, x0 = (int)fx;
    int y1 = y0 + 1,  x1 = x0 + 1;
    float wy = py - fy, wx = px - fx;

    // per-corner validity (zero padding) + clamped indices
    float my0 = (y0 >= 0 && y0 < HN) ? 1.f : 0.f;
    float my1 = (y1 >= 0 && y1 < HN) ? 1.f : 0.f;
    float mx0 = (x0 >= 0 && x0 < WN) ? 1.f : 0.f;
    float mx1 = (x1 >= 0 && x1 < WN) ? 1.f : 0.f;
    int y0c = min(max(y0, 0), HN - 1);
    int y1c = min(max(y1, 0), HN - 1);
    int x0c = min(max(x0, 0), WN - 1);
    int x1c = min(max(x1, 0), WN - 1);

    int i00 = y0c * WN + x0c;
    int i01 = y0c * WN + x1c;
    int i10 = y1c * WN + x0c;
    int i11 = y1c * WN + x1c;

    float w00 = (1.f - wy) * (1.f - wx) * my0 * mx0;
    float w01 = (1.f - wy) * wx          * my0 * mx1;
    float w10 = wy * (1.f - wx)          * my1 * mx0;
    float w11 = wy * wx                  * my1 * mx1;

    const float* xb = x + ((size_t)(b * CN + g * CGN)) * HW;
    float* outp = g_col + ((size_t)b * KD + (size_t)g * CGN * K2 + k) * HW + hw;

    #pragma unroll 4
    for (int c = 0; c < CGN; c++) {
        const float* xc = xb + (size_t)c * HW;
        float v = w00 * xc[i00] + w01 * xc[i01] + w10 * xc[i10] + w11 * xc[i11];
        outp[(size_t)c * K2 * HW] = v;
    }
}

// ---------------------------------------------------------------------------
// Kernel 2: per-batch GEMM  out[b] = Wd[256,2304] @ col[b][2304,4096]
// 128x128 block tile, BK=8, 256 threads, 8x8 microtile.
// Double-buffered shared memory, register-staged global prefetch:
// one __syncthreads per K-iteration.
// ---------------------------------------------------------------------------
__global__ void __launch_bounds__(256, 2)
gemm_kernel(const float* __restrict__ Wd, float* __restrict__ out)
{
    const int b  = blockIdx.z;
    const float* Bm = g_col + (size_t)b * KD * HW;
    float*       Om = out   + (size_t)b * ON * HW;

    __shared__ float As[2][8][128];
    __shared__ float Bs[2][8][128];

    const int tid = threadIdx.x;
    const int tx  = tid & 15;       // 0..15 -> n microtile
    const int ty  = tid >> 4;       // 0..15 -> m microtile
    const int m0  = blockIdx.y * 128;
    const int n0  = blockIdx.x * 128;

    // A tile load map: thread -> (row, 4 consecutive k)
    const int aRow = tid >> 1;
    const int aK   = (tid & 1) * 4;
    // B tile load map: thread -> (k, 4 consecutive n)
    const int bK = tid >> 5;
    const int bN = (tid & 31) * 4;

    const float* aPtr = Wd + (size_t)(m0 + aRow) * KD + aK;
    const float* bPtr = Bm + (size_t)bK * HW + n0 + bN;

    float acc[8][8];
    #pragma unroll
    for (int i = 0; i < 8; i++)
        #pragma unroll
        for (int j = 0; j < 8; j++) acc[i][j] = 0.f;

    // preload tile 0 into smem buffer 0
    {
        float4 a = *(const float4*)(aPtr);
        As[0][aK + 0][aRow] = a.x;
        As[0][aK + 1][aRow] = a.y;
        As[0][aK + 2][aRow] = a.z;
        As[0][aK + 3][aRow] = a.w;
        *(float4*)&Bs[0][bK][bN] = *(const float4*)(bPtr);
    }
    __syncthreads();

    int buf = 0;
    for (int k0 = 0; k0 < KD; k0 += 8) {
        const bool has_next = (k0 + 8) < KD;
        float4 a_next, b_next;
        if (has_next) {
            a_next = *(const float4*)(aPtr + (k0 + 8));
            b_next = *(const float4*)(bPtr + (size_t)(k0 + 8) * HW);
        }

        #pragma unroll
        for (int kk = 0; kk < 8; kk++) {
            float ra[8], rb[8];
            #pragma unroll
            for (int i = 0; i < 8; i++) ra[i] = As[buf][kk][ty * 8 + i];
            #pragma unroll
            for (int j = 0; j < 8; j++) rb[j] = Bs[buf][kk][tx * 8 + j];
            #pragma unroll
            for (int i = 0; i < 8; i++)
                #pragma unroll
                for (int j = 0; j < 8; j++)
                    acc[i][j] = fmaf(ra[i], rb[j], acc[i][j]);
        }

        if (has_next) {
            int nb = buf ^ 1;
            As[nb][aK + 0][aRow] = a_next.x;
            As[nb][aK + 1][aRow] = a_next.y;
            As[nb][aK + 2][aRow] = a_next.z;
            As[nb][aK + 3][aRow] = a_next.w;
            *(float4*)&Bs[nb][bK][bN] = b_next;
            __syncthreads();
            buf = nb;
        }
    }

    #pragma unroll
    for (int i = 0; i < 8; i++) {
        float* op = Om + (size_t)(m0 + ty * 8 + i) * HW + n0 + tx * 8;
        *(float4*)(op + 0) = make_float4(acc[i][0], acc[i][1], acc[i][2], acc[i][3]);
        *(float4*)(op + 4) = make_float4(acc[i][4], acc[i][5], acc[i][6], acc[i][7]);
    }
}

// ---------------------------------------------------------------------------
// Kernel 3: GroupNorm statistics. One block per (b, group); each group's data
// is a contiguous 32768-float span of y.
// ---------------------------------------------------------------------------
__global__ void gn_stats_kernel(const float* __restrict__ y)
{
    const int bg = blockIdx.x;                       // b*32 + group
    const float* p = y + (size_t)bg * GRP_ELEMS;

    float s = 0.f, ss = 0.f;
    for (int i = threadIdx.x * 4; i < GRP_ELEMS; i += blockDim.x * 4) {
        float4 v = *(const float4*)(p + i);
        s  += v.x + v.y + v.z + v.w;
        ss += v.x * v.x + v.y * v.y + v.z * v.z + v.w * v.w;
    }
    #pragma unroll
    for (int off = 16; off > 0; off >>= 1) {
        s  += __shfl_down_sync(0xffffffffu, s,  off);
        ss += __shfl_down_sync(0xffffffffu, ss, off);
    }
    __shared__ float sh_s[8], sh_ss[8];
    int wid = threadIdx.x >> 5, lid = threadIdx.x & 31;
    if (lid == 0) { sh_s[wid] = s; sh_ss[wid] = ss; }
    __syncthreads();
    if (wid == 0) {
        s  = (lid < 8) ? sh_s[lid]  : 0.f;
        ss = (lid < 8) ? sh_ss[lid] : 0.f;
        #pragma unroll
        for (int off = 4; off > 0; off >>= 1) {
            s  += __shfl_down_sync(0xffffffffu, s,  off);
            ss += __shfl_down_sync(0xffffffffu, ss, off);
        }
        if (lid == 0) {
            float mu  = s * (1.f / GRP_ELEMS);
            float var = ss * (1.f / GRP_ELEMS) - mu * mu;
            g_mu[bg]   = mu;
            g_rstd[bg] = rsqrtf(var + EPS);
        }
    }
}

// ---------------------------------------------------------------------------
// Kernel 4: normalize + affine + ReLU, in place, float4 vectorized.
// ---------------------------------------------------------------------------
__global__ void gn_norm_kernel(float* __restrict__ y,
                               const float* __restrict__ gamma,
                               const float* __restrict__ beta)
{
    int idx = blockIdx.x * blockDim.x + threadIdx.x;   // float4 index
    int bg = idx >> 13;             // 8192 float4 per (b,group)
    int c  = (idx >> 10) & 255;     // 1024 float4 per channel
    float mu = g_mu[bg];
    float r  = g_rstd[bg];
    float a  = r * gamma[c];
    float bb = beta[c] - mu * a;

    float4 v = *(float4*)(y + (size_t)idx * 4);
    v.x = fmaxf(fmaf(v.x, a, bb), 0.f);
    v.y = fmaxf(fmaf(v.y, a, bb), 0.f);
    v.z = fmaxf(fmaf(v.z, a, bb), 0.f);
    v.w = fmaxf(fmaf(v.w, a, bb), 0.f);
    *(float4*)(y + (size_t)idx * 4) = v;
}

// ---------------------------------------------------------------------------
// Launcher
// inputs (metadata order): x[8,256,64,64], x_off[8,4,64,64], w_offset[72,4],
//                          w_deform[256,256,3,3], gamma[256], beta[256]
// output: float32 [8,256,64,64]
// ---------------------------------------------------------------------------
extern "C" void kernel_launch(void* const* d_in, const int* in_sizes, int n_in,
                              void* d_out, int out_size)
{
    const float* x        = (const float*)d_in[0];
    const float* x_off    = (const float*)d_in[1];
    const float* w_offset = (const float*)d_in[2];
    const float* w_deform = (const float*)d_in[3];
    const float* gamma    = (const float*)d_in[4];
    const float* beta     = (const float*)d_in[5];
    float* out = (float*)d_out;

    // 1) deformable im2col (fused offset projection)
    {
        int total = BN * DGN * K2 * HW;      // 1179648
        im2col_kernel<<<total / 256, 256>>>(x, x_off, w_offset);
    }
    // 2) GEMM per batch
    {
        dim3 grid(HW / 128, ON / 128, BN);   // (32, 2, 8)
        gemm_kernel<<<grid, 256>>>(w_deform, out);
    }
    // 3) GroupNorm stats
    gn_stats_kernel<<<BN * GN_GROUPS, 256>>>(out);
    // 4) normalize + ReLU
    {
        int total4 = BN * ON * HW / 4;       // 2097152
        gn_norm_kernel<<<total4 / 256, 256>>>(out, gamma, beta);
    }
}

// round 5
// speedup vs baseline: 1.1118x; 1.1118x over previous
#include <cuda_runtime.h>
#include <cuda_bf16.h>
#include <stdint.h>
#include <math.h>

// Problem constants
#define BN 8
#define CN 256
#define ON 256
#define HN 64
#define WN 64
#define HW 4096
#define K2 9
#define DGN 4
#define CGN 64
#define KD 2304          // CN*K2 (GEMM reduction dim)
#define GN_GROUPS 32
#define GRP_ELEMS 32768
#define EPS 1e-5f

// GEMM tiling
#define BM 128
#define BNT 64
#define BK 32
#define NCH (KD / BK)        // 72
#define ROWB 80              // padded SMEM row stride (bytes) for 32 bf16
#define T_A (BM * ROWB)      // 10240 B per A tile
#define T_B (BNT * ROWB)     // 5120 B per B tile
#define STAGE_B (2 * T_A + 2 * T_B)   // 30720 B per stage
#define SMEM_TOTAL (2 * STAGE_B)      // 61440 B

// ---------------------------------------------------------------------------
// Device scratch
// ---------------------------------------------------------------------------
__device__ __nv_bfloat16 g_colh[(size_t)BN * HW * KD];   // [b][hw][kd]
__device__ __nv_bfloat16 g_coll[(size_t)BN * HW * KD];
__device__ __nv_bfloat16 g_wh[(size_t)ON * KD];
__device__ __nv_bfloat16 g_wl[(size_t)ON * KD];
__device__ float g_mu[BN * GN_GROUPS];
__device__ float g_rstd[BN * GN_GROUPS];

// ---------------------------------------------------------------------------
// PTX helpers (stable sm_80+ features only)
// ---------------------------------------------------------------------------
__device__ __forceinline__ uint32_t smem_u32(const void* p) {
    uint32_t a;
    asm("{ .reg .u64 t; cvta.to.shared.u64 t, %1; cvt.u32.u64 %0, t; }"
        : "=r"(a) : "l"(p));
    return a;
}
__device__ __forceinline__ void cp16(uint32_t s, const void* g) {
    asm volatile("cp.async.cg.shared.global [%0], [%1], 16;"
                 :: "r"(s), "l"(g) : "memory");
}
#define CP_COMMIT() asm volatile("cp.async.commit_group;" ::: "memory")
#define CP_WAIT(n)  asm volatile("cp.async.wait_group %0;" :: "n"(n) : "memory")

__device__ __forceinline__ void ldm_x4(uint32_t* r, uint32_t addr) {
    asm volatile("ldmatrix.sync.aligned.m8n8.x4.shared.b16 {%0,%1,%2,%3}, [%4];"
                 : "=r"(r[0]), "=r"(r[1]), "=r"(r[2]), "=r"(r[3]) : "r"(addr));
}
__device__ __forceinline__ void mma_bf16(float* c, const uint32_t* a,
                                         const uint32_t* b) {
    asm volatile(
        "mma.sync.aligned.m16n8k16.row.col.f32.bf16.bf16.f32 "
        "{%0,%1,%2,%3}, {%4,%5,%6,%7}, {%8,%9}, {%0,%1,%2,%3};"
        : "+f"(c[0]), "+f"(c[1]), "+f"(c[2]), "+f"(c[3])
        : "r"(a[0]), "r"(a[1]), "r"(a[2]), "r"(a[3]), "r"(b[0]), "r"(b[1]));
}

// ---------------------------------------------------------------------------
// Kernel A: split weights into bf16 hi/lo. w flat [O][KD], kd = c*9+ky*3+kx.
// ---------------------------------------------------------------------------
__global__ void wsplit_kernel(const float* __restrict__ w)
{
    int i = blockIdx.x * blockDim.x + threadIdx.x;
    float v = w[i];
    __nv_bfloat16 h = __float2bfloat16(v);
    __nv_bfloat16 l = __float2bfloat16(v - __bfloat162float(h));
    g_wh[i] = h;
    g_wl[i] = l;
}

// ---------------------------------------------------------------------------
// Kernel B: fused offset-projection + deformable im2col -> bf16 hi/lo,
// K-contiguous: col[b][hw][kd], kd = g*576 + c*9 + k.
// ---------------------------------------------------------------------------
#define THW 32
__global__ void __launch_bounds__(256)
im2col2_kernel(const float* __restrict__ x,
               const float* __restrict__ x_off,
               const float* __restrict__ w_offset)
{
    const int b   = blockIdx.z;
    const int g   = blockIdx.y;
    const int hw0 = blockIdx.x * THW;
    const int tid = threadIdx.x;

    __shared__ int   s_i[4][THW * 9];
    __shared__ float s_w[4][THW * 9];

    for (int p = tid; p < THW * 9; p += 256) {
        int hwl = p / 9;
        int k   = p - hwl * 9;
        int hw  = hw0 + hwl;
        int h = hw >> 6, w = hw & 63;

        const float* xo = x_off + (size_t)b * 4 * HW + hw;
        float o0 = xo[0], o1 = xo[HW], o2 = xo[2 * HW], o3 = xo[3 * HW];
        const float* wo = w_offset + (size_t)((g * K2 + k) * 2) * 4;
        float offy = wo[0] * o0 + wo[1] * o1 + wo[2] * o2 + wo[3] * o3;
        float offx = wo[4] * o0 + wo[5] * o1 + wo[6] * o2 + wo[7] * o3;

        float py = (float)(h + k / 3 - 1) + offy;
        float px = (float)(w + k % 3 - 1) + offx;
        float fy = floorf(py), fx = floorf(px);
        int y0 = (int)fy, x0 = (int)fx, y1 = y0 + 1, x1 = x0 + 1;
        float wy = py - fy, wx = px - fx;

        float my0 = (y0 >= 0 && y0 < HN) ? 1.f : 0.f;
        float my1 = (y1 >= 0 && y1 < HN) ? 1.f : 0.f;
        float mx0 = (x0 >= 0 && x0 < WN) ? 1.f : 0.f;
        float mx1 = (x1 >= 0 && x1 < WN) ? 1.f : 0.f;
        int y0c = min(max(y0, 0), HN - 1), y1c = min(max(y1, 0), HN - 1);
        int x0c = min(max(x0, 0), WN - 1), x1c = min(max(x1, 0), WN - 1);

        s_i[0][p] = y0c * WN + x0c;
        s_i[1][p] = y0c * WN + x1c;
        s_i[2][p] = y1c * WN + x0c;
        s_i[3][p] = y1c * WN + x1c;
        s_w[0][p] = (1.f - wy) * (1.f - wx) * my0 * mx0;
        s_w[1][p] = (1.f - wy) * wx          * my0 * mx1;
        s_w[2][p] = wy * (1.f - wx)          * my1 * mx0;
        s_w[3][p] = wy * wx                  * my1 * mx1;
    }
    __syncthreads();

    const float* xg = x + ((size_t)(b * CN + g * CGN)) * HW;
    __nv_bfloat16* outh = g_colh + ((size_t)b * HW) * KD + (size_t)g * 576;
    __nv_bfloat16* outl = g_coll + ((size_t)b * HW) * KD + (size_t)g * 576;

    for (int p = tid; p < THW * 288; p += 256) {
        int hwl = p / 288;
        int pk  = p - hwl * 288;
        int kd0 = pk * 2;
        int c0 = kd0 / 9, k0 = kd0 - 9 * c0;
        int kd1 = kd0 + 1;
        int c1 = kd1 / 9, k1 = kd1 - 9 * c1;

        int pa = hwl * 9 + k0;
        int pb = hwl * 9 + k1;
        const float* xc0 = xg + (size_t)c0 * HW;
        const float* xc1 = xg + (size_t)c1 * HW;

        float v0 = s_w[0][pa] * xc0[s_i[0][pa]] + s_w[1][pa] * xc0[s_i[1][pa]] +
                   s_w[2][pa] * xc0[s_i[2][pa]] + s_w[3][pa] * xc0[s_i[3][pa]];
        float v1 = s_w[0][pb] * xc1[s_i[0][pb]] + s_w[1][pb] * xc1[s_i[1][pb]] +
                   s_w[2][pb] * xc1[s_i[2][pb]] + s_w[3][pb] * xc1[s_i[3][pb]];

        __nv_bfloat16 h0 = __float2bfloat16(v0);
        __nv_bfloat16 l0 = __float2bfloat16(v0 - __bfloat162float(h0));
        __nv_bfloat16 h1 = __float2bfloat16(v1);
        __nv_bfloat16 l1 = __float2bfloat16(v1 - __bfloat162float(h1));

        size_t off = (size_t)(hw0 + hwl) * KD + kd0;
        __nv_bfloat162 th; th.x = h0; th.y = h1;
        __nv_bfloat162 tl; tl.x = l0; tl.y = l1;
        *(__nv_bfloat162*)(outh + off) = th;
        *(__nv_bfloat162*)(outl + off) = tl;
    }
}

// ---------------------------------------------------------------------------
// Kernel C: mma.sync bf16 split GEMM.
// out[b][m][n] = sum_k W[m][k] * col[b][n][k],
// C = Ah*Bh + Ah*Bl + Al*Bh accumulated in fp32.
// CTA tile 128x64, 8 warps (4 m x 2 n), per warp 32x32 (2 mf x 4 nf).
// BK=32 chunks, cp.async double buffering, ldmatrix fragments.
// ---------------------------------------------------------------------------
__global__ void __launch_bounds__(256, 2)
gemm_mma_kernel(float* __restrict__ out)
{
    extern __shared__ char smem[];
    const uint32_t sb = smem_u32(smem);
    const int tid = threadIdx.x;
    const int wid = tid >> 5, lane = tid & 31;
    const int warp_m = wid & 3;        // 0..3 -> 32 rows each
    const int warp_n = wid >> 2;       // 0..1 -> 32 cols each
    const int n0 = blockIdx.x * BNT;
    const int m0 = blockIdx.y * BM;
    const int b  = blockIdx.z;

    const __nv_bfloat16* Ah = g_wh + (size_t)m0 * KD;
    const __nv_bfloat16* Al = g_wl + (size_t)m0 * KD;
    const __nv_bfloat16* Bh = g_colh + ((size_t)(b * HW + n0)) * KD;
    const __nv_bfloat16* Bl = g_coll + ((size_t)(b * HW + n0)) * KD;

    // per-thread cp.async map
    // A tiles: 512 16B-segments; this thread does tid and tid+256
    const int arow0 = tid >> 2,        acs0 = (tid & 3);
    const int arow1 = (tid + 256) >> 2, acs1 = (tid & 3);
    // B tiles: 256 segments; one per thread
    const int brow = tid >> 2, bcs = (tid & 3);

    float c[2][4][4];
    #pragma unroll
    for (int i = 0; i < 2; i++)
        #pragma unroll
        for (int j = 0; j < 4; j++)
            #pragma unroll
            for (int q = 0; q < 4; q++) c[i][j][q] = 0.f;

    // prologue: chunk 0 -> stage 0
    {
        uint32_t st = sb;
        cp16(st + 0 * T_A + arow0 * ROWB + acs0 * 16, Ah + (size_t)arow0 * KD + acs0 * 8);
        cp16(st + 0 * T_A + arow1 * ROWB + acs1 * 16, Ah + (size_t)arow1 * KD + acs1 * 8);
        cp16(st + 1 * T_A + arow0 * ROWB + acs0 * 16, Al + (size_t)arow0 * KD + acs0 * 8);
        cp16(st + 1 * T_A + arow1 * ROWB + acs1 * 16, Al + (size_t)arow1 * KD + acs1 * 8);
        cp16(st + 2 * T_A + brow * ROWB + bcs * 16,   Bh + (size_t)brow * KD + bcs * 8);
        cp16(st + 2 * T_A + T_B + brow * ROWB + bcs * 16, Bl + (size_t)brow * KD + bcs * 8);
        CP_COMMIT();
    }

    for (int ch = 0; ch < NCH; ch++) {
        const int cur = ch & 1;
        if (ch + 1 < NCH) {
            const int k0 = (ch + 1) * BK;
            uint32_t st = sb + (cur ^ 1) * STAGE_B;
            cp16(st + 0 * T_A + arow0 * ROWB + acs0 * 16, Ah + (size_t)arow0 * KD + k0 + acs0 * 8);
            cp16(st + 0 * T_A + arow1 * ROWB + acs1 * 16, Ah + (size_t)arow1 * KD + k0 + acs1 * 8);
            cp16(st + 1 * T_A + arow0 * ROWB + acs0 * 16, Al + (size_t)arow0 * KD + k0 + acs0 * 8);
            cp16(st + 1 * T_A + arow1 * ROWB + acs1 * 16, Al + (size_t)arow1 * KD + k0 + acs1 * 8);
            cp16(st + 2 * T_A + brow * ROWB + bcs * 16,   Bh + (size_t)brow * KD + k0 + bcs * 8);
            cp16(st + 2 * T_A + T_B + brow * ROWB + bcs * 16, Bl + (size_t)brow * KD + k0 + bcs * 8);
            CP_COMMIT();
            CP_WAIT(1);
        } else {
            CP_WAIT(0);
        }
        __syncthreads();

        const uint32_t st = sb + cur * STAGE_B;
        #pragma unroll
        for (int ks = 0; ks < 2; ks++) {
            // A fragment addresses: lanes 0-15 rows, lanes 16-31 +16B
            uint32_t a_off = (uint32_t)((warp_m * 32 + (lane & 15)) * ROWB
                                        + ks * 32 + ((lane >> 4) << 4));
            uint32_t ah[2][4], al[2][4];
            #pragma unroll
            for (int mf = 0; mf < 2; mf++) {
                ldm_x4(ah[mf], st + 0 * T_A + a_off + mf * 16 * ROWB);
                ldm_x4(al[mf], st + 1 * T_A + a_off + mf * 16 * ROWB);
            }
            // B fragment addresses
            uint32_t b_off = (uint32_t)((warp_n * 32 + (lane & 7) + ((lane >> 4) << 3)) * ROWB
                                        + ks * 32 + (((lane >> 3) & 1) << 4));
            uint32_t bh[4][2], bl[4][2];
            #pragma unroll
            for (int nfp = 0; nfp < 2; nfp++) {
                uint32_t r[4];
                ldm_x4(r, st + 2 * T_A + b_off + nfp * 16 * ROWB);
                bh[nfp * 2][0] = r[0]; bh[nfp * 2][1] = r[1];
                bh[nfp * 2 + 1][0] = r[2]; bh[nfp * 2 + 1][1] = r[3];
                ldm_x4(r, st + 2 * T_A + T_B + b_off + nfp * 16 * ROWB);
                bl[nfp * 2][0] = r[0]; bl[nfp * 2][1] = r[1];
                bl[nfp * 2 + 1][0] = r[2]; bl[nfp * 2 + 1][1] = r[3];
            }
            #pragma unroll
            for (int mf = 0; mf < 2; mf++)
                #pragma unroll
                for (int nf = 0; nf < 4; nf++) {
                    mma_bf16(c[mf][nf], ah[mf], bh[nf]);
                    mma_bf16(c[mf][nf], ah[mf], bl[nf]);
                    mma_bf16(c[mf][nf], al[mf], bh[nf]);
                }
        }
        __syncthreads();
    }

    // Epilogue: m16n8 C fragment -> out
    #pragma unroll
    for (int mf = 0; mf < 2; mf++)
        #pragma unroll
        for (int nf = 0; nf < 4; nf++) {
            int row = m0 + warp_m * 32 + mf * 16 + (lane >> 2);
            int col = n0 + warp_n * 32 + nf * 8 + 2 * (lane & 3);
            float* op0 = out + ((size_t)(b * ON + row)) * HW + col;
            float* op1 = out + ((size_t)(b * ON + row + 8)) * HW + col;
            *(float2*)op0 = make_float2(c[mf][nf][0], c[mf][nf][1]);
            *(float2*)op1 = make_float2(c[mf][nf][2], c[mf][nf][3]);
        }
}

// ---------------------------------------------------------------------------
// GroupNorm stats + normalize (validated)
// ---------------------------------------------------------------------------
__global__ void gn_stats_kernel(const float* __restrict__ y)
{
    const int bg = blockIdx.x;
    const float* p = y + (size_t)bg * GRP_ELEMS;
    float s = 0.f, ss = 0.f;
    for (int i = threadIdx.x * 4; i < GRP_ELEMS; i += blockDim.x * 4) {
        float4 v = *(const float4*)(p + i);
        s  += v.x + v.y + v.z + v.w;
        ss += v.x * v.x + v.y * v.y + v.z * v.z + v.w * v.w;
    }
    #pragma unroll
    for (int off = 16; off > 0; off >>= 1) {
        s  += __shfl_down_sync(0xffffffffu, s,  off);
        ss += __shfl_down_sync(0xffffffffu, ss, off);
    }
    __shared__ float sh_s[8], sh_ss[8];
    int wid = threadIdx.x >> 5, lid = threadIdx.x & 31;
    if (lid == 0) { sh_s[wid] = s; sh_ss[wid] = ss; }
    __syncthreads();
    if (wid == 0) {
        s  = (lid < 8) ? sh_s[lid]  : 0.f;
        ss = (lid < 8) ? sh_ss[lid] : 0.f;
        #pragma unroll
        for (int off = 4; off > 0; off >>= 1) {
            s  += __shfl_down_sync(0xffffffffu, s,  off);
            ss += __shfl_down_sync(0xffffffffu, ss, off);
        }
        if (lid == 0) {
            float mu  = s * (1.f / GRP_ELEMS);
            float var = ss * (1.f / GRP_ELEMS) - mu * mu;
            g_mu[bg]   = mu;
            g_rstd[bg] = rsqrtf(var + EPS);
        }
    }
}

__global__ void gn_norm_kernel(float* __restrict__ y,
                               const float* __restrict__ gamma,
                               const float* __restrict__ beta)
{
    int idx = blockIdx.x * blockDim.x + threadIdx.x;
    int bg = idx >> 13;
    int c  = (idx >> 10) & 255;
    float mu = g_mu[bg];
    float r  = g_rstd[bg];
    float a  = r * gamma[c];
    float bb = beta[c] - mu * a;
    float4 v = *(float4*)(y + (size_t)idx * 4);
    v.x = fmaxf(fmaf(v.x, a, bb), 0.f);
    v.y = fmaxf(fmaf(v.y, a, bb), 0.f);
    v.z = fmaxf(fmaf(v.z, a, bb), 0.f);
    v.w = fmaxf(fmaf(v.w, a, bb), 0.f);
    *(float4*)(y + (size_t)idx * 4) = v;
}

// ---------------------------------------------------------------------------
// Launcher
// ---------------------------------------------------------------------------
extern "C" void kernel_launch(void* const* d_in, const int* in_sizes, int n_in,
                              void* d_out, int out_size)
{
    const float* x        = (const float*)d_in[0];
    const float* x_off    = (const float*)d_in[1];
    const float* w_offset = (const float*)d_in[2];
    const float* w_deform = (const float*)d_in[3];
    const float* gamma    = (const float*)d_in[4];
    const float* beta     = (const float*)d_in[5];
    float* out = (float*)d_out;

    cudaFuncSetAttribute(gemm_mma_kernel,
                         cudaFuncAttributeMaxDynamicSharedMemorySize,
                         SMEM_TOTAL);

    // 1) weight split
    wsplit_kernel<<<(ON * KD) / 256, 256>>>(w_deform);
    // 2) deformable im2col -> bf16 hi/lo, K-contiguous
    {
        dim3 grid(HW / THW, DGN, BN);        // (128, 4, 8)
        im2col2_kernel<<<grid, 256>>>(x, x_off, w_offset);
    }
    // 3) tensor-core GEMM (mma.sync)
    {
        dim3 grid(HW / BNT, ON / BM, BN);    // (64, 2, 8)
        gemm_mma_kernel<<<grid, 256, SMEM_TOTAL>>>(out);
    }
    // 4) GroupNorm
    gn_stats_kernel<<<BN * GN_GROUPS, 256>>>(out);
    gn_norm_kernel<<<(BN * ON * HW / 4) / 256, 256>>>(out, gamma, beta);
}

// round 6
// speedup vs baseline: 1.6363x; 1.4718x over previous
#include <cuda_runtime.h>
#include <cuda_bf16.h>
#include <stdint.h>
#include <math.h>

// Problem constants
#define BN 8
#define CN 256
#define ON 256
#define HN 64
#define WN 64
#define HW 4096
#define K2 9
#define DGN 4
#define CGN 64
#define KD 2304          // CN*K2 (GEMM reduction dim)
#define GN_GROUPS 32
#define GRP_ELEMS 32768
#define EPS 1e-5f

// GEMM tiling
#define BM 128
#define BNT 64
#define BK 32
#define NCH (KD / BK)        // 72
#define ROWB 80              // padded SMEM row stride (bytes) for 32 bf16
#define T_A (BM * ROWB)      // 10240 B per A tile
#define T_B (BNT * ROWB)     // 5120 B per B tile
#define STAGE_B (2 * T_A + 2 * T_B)   // 30720 B per stage
#define SMEM_TOTAL (2 * STAGE_B)      // 61440 B

// ---------------------------------------------------------------------------
// Device scratch
// ---------------------------------------------------------------------------
__device__ __nv_bfloat16 g_colh[(size_t)BN * HW * KD];   // [b][hw][kd]
__device__ __nv_bfloat16 g_coll[(size_t)BN * HW * KD];
__device__ __nv_bfloat16 g_wh[(size_t)ON * KD];
__device__ __nv_bfloat16 g_wl[(size_t)ON * KD];
__device__ float g_mu[BN * GN_GROUPS];
__device__ float g_rstd[BN * GN_GROUPS];

// ---------------------------------------------------------------------------
// PTX helpers (stable sm_80+ features only)
// ---------------------------------------------------------------------------
__device__ __forceinline__ uint32_t smem_u32(const void* p) {
    uint32_t a;
    asm("{ .reg .u64 t; cvta.to.shared.u64 t, %1; cvt.u32.u64 %0, t; }"
        : "=r"(a) : "l"(p));
    return a;
}
__device__ __forceinline__ void cp16(uint32_t s, const void* g) {
    asm volatile("cp.async.cg.shared.global [%0], [%1], 16;"
                 :: "r"(s), "l"(g) : "memory");
}
#define CP_COMMIT() asm volatile("cp.async.commit_group;" ::: "memory")
#define CP_WAIT(n)  asm volatile("cp.async.wait_group %0;" :: "n"(n) : "memory")

__device__ __forceinline__ void ldm_x4(uint32_t* r, uint32_t addr) {
    asm volatile("ldmatrix.sync.aligned.m8n8.x4.shared.b16 {%0,%1,%2,%3}, [%4];"
                 : "=r"(r[0]), "=r"(r[1]), "=r"(r[2]), "=r"(r[3]) : "r"(addr));
}
__device__ __forceinline__ void mma_bf16(float* c, const uint32_t* a,
                                         const uint32_t* b) {
    asm volatile(
        "mma.sync.aligned.m16n8k16.row.col.f32.bf16.bf16.f32 "
        "{%0,%1,%2,%3}, {%4,%5,%6,%7}, {%8,%9}, {%0,%1,%2,%3};"
        : "+f"(c[0]), "+f"(c[1]), "+f"(c[2]), "+f"(c[3])
        : "r"(a[0]), "r"(a[1]), "r"(a[2]), "r"(a[3]), "r"(b[0]), "r"(b[1]));
}

// ---------------------------------------------------------------------------
// Kernel A: split weights into bf16 hi/lo. w flat [O][KD], kd = c*9+ky*3+kx.
// ---------------------------------------------------------------------------
__global__ void wsplit_kernel(const float* __restrict__ w)
{
    int i = blockIdx.x * blockDim.x + threadIdx.x;
    float v = w[i];
    __nv_bfloat16 h = __float2bfloat16(v);
    __nv_bfloat16 l = __float2bfloat16(v - __bfloat162float(h));
    g_wh[i] = h;
    g_wl[i] = l;
}

// ---------------------------------------------------------------------------
// Kernel B (v3): fused offset-projection + deformable im2col with SMEM-staged
// transpose. Block = (b, g, 16 hw). Gathers from x are coalesced (half-warp =
// 16 hw lanes within ONE channel); scatter goes to SMEM; gmem writes are
// K-contiguous 1152B bursts. Output layout unchanged: col[b][hw][kd],
// kd = g*576 + c*9 + k, as bf16 hi/lo.
// ---------------------------------------------------------------------------
#define V3HW 16
#define QP   288               // kd pairs per (g) slice: 576/2
#define SROW 289               // uint32 row stride (289 mod 32 == 1)
__global__ void __launch_bounds__(256)
im2col3_kernel(const float* __restrict__ x,
               const float* __restrict__ x_off,
               const float* __restrict__ w_offset)
{
    const int b   = blockIdx.z;
    const int g   = blockIdx.y;
    const int hw0 = blockIdx.x * V3HW;
    const int tid = threadIdx.x;

    __shared__ int      s_i[4][V3HW * 9];
    __shared__ float    s_w[4][V3HW * 9];
    __shared__ uint32_t s_h[V3HW * SROW];    // packed bf16x2 (kd even, kd odd)
    __shared__ uint32_t s_l[V3HW * SROW];

    // Phase 1: bilinear params for 16 hw x 9 k (validated math)
    if (tid < V3HW * 9) {
        int p   = tid;
        int hwl = p / 9;
        int k   = p - hwl * 9;
        int hw  = hw0 + hwl;
        int h = hw >> 6, w = hw & 63;

        const float* xo = x_off + (size_t)b * 4 * HW + hw;
        float o0 = xo[0], o1 = xo[HW], o2 = xo[2 * HW], o3 = xo[3 * HW];
        const float* wo = w_offset + (size_t)((g * K2 + k) * 2) * 4;
        float offy = wo[0] * o0 + wo[1] * o1 + wo[2] * o2 + wo[3] * o3;
        float offx = wo[4] * o0 + wo[5] * o1 + wo[6] * o2 + wo[7] * o3;

        float py = (float)(h + k / 3 - 1) + offy;
        float px = (float)(w + k % 3 - 1) + offx;
        float fy = floorf(py), fx = floorf(px);
        int y0 = (int)fy, x0 = (int)fx, y1 = y0 + 1, x1 = x0 + 1;
        float wy = py - fy, wx = px - fx;

        float my0 = (y0 >= 0 && y0 < HN) ? 1.f : 0.f;
        float my1 = (y1 >= 0 && y1 < HN) ? 1.f : 0.f;
        float mx0 = (x0 >= 0 && x0 < WN) ? 1.f : 0.f;
        float mx1 = (x1 >= 0 && x1 < WN) ? 1.f : 0.f;
        int y0c = min(max(y0, 0), HN - 1), y1c = min(max(y1, 0), HN - 1);
        int x0c = min(max(x0, 0), WN - 1), x1c = min(max(x1, 0), WN - 1);

        s_i[0][p] = y0c * WN + x0c;
        s_i[1][p] = y0c * WN + x1c;
        s_i[2][p] = y1c * WN + x0c;
        s_i[3][p] = y1c * WN + x1c;
        s_w[0][p] = (1.f - wy) * (1.f - wx) * my0 * mx0;
        s_w[1][p] = (1.f - wy) * wx          * my0 * mx1;
        s_w[2][p] = wy * (1.f - wx)          * my1 * mx0;
        s_w[3][p] = wy * wx                  * my1 * mx1;
    }
    __syncthreads();

    const float* xg = x + ((size_t)(b * CN + g * CGN)) * HW;

    // Phase 2: 18 iters; half-warp = one kd-pair (c0,k0 / c1,k1), 16 hw lanes.
    #pragma unroll 2
    for (int i = 0; i < 18; i++) {
        int qp  = i * 16 + (tid >> 4);     // 0..287
        int hwl = tid & 15;
        int kd0 = qp * 2;
        int c0 = kd0 / 9, k0 = kd0 - 9 * c0;
        int kd1 = kd0 + 1;
        int c1 = kd1 / 9, k1 = kd1 - 9 * c1;

        int pa = hwl * 9 + k0;
        int pb = hwl * 9 + k1;
        const float* xc0 = xg + (size_t)c0 * HW;
        const float* xc1 = xg + (size_t)c1 * HW;

        float v0 = s_w[0][pa] * xc0[s_i[0][pa]] + s_w[1][pa] * xc0[s_i[1][pa]] +
                   s_w[2][pa] * xc0[s_i[2][pa]] + s_w[3][pa] * xc0[s_i[3][pa]];
        float v1 = s_w[0][pb] * xc1[s_i[0][pb]] + s_w[1][pb] * xc1[s_i[1][pb]] +
                   s_w[2][pb] * xc1[s_i[2][pb]] + s_w[3][pb] * xc1[s_i[3][pb]];

        __nv_bfloat16 h0 = __float2bfloat16(v0);
        __nv_bfloat16 l0 = __float2bfloat16(v0 - __bfloat162float(h0));
        __nv_bfloat16 h1 = __float2bfloat16(v1);
        __nv_bfloat16 l1 = __float2bfloat16(v1 - __bfloat162float(h1));

        uint32_t ph = ((uint32_t)__bfloat16_as_ushort(h1) << 16) |
                       (uint32_t)__bfloat16_as_ushort(h0);
        uint32_t pl = ((uint32_t)__bfloat16_as_ushort(l1) << 16) |
                       (uint32_t)__bfloat16_as_ushort(l0);
        s_h[hwl * SROW + qp] = ph;
        s_l[hwl * SROW + qp] = pl;
    }
    __syncthreads();

    // Phase 3: coalesced writeout, 288-word (1152B) bursts per hw row.
    uint32_t* gh = (uint32_t*)(g_colh + ((size_t)b * HW) * KD + (size_t)g * 576);
    uint32_t* gl = (uint32_t*)(g_coll + ((size_t)b * HW) * KD + (size_t)g * 576);
    for (int idx = tid; idx < V3HW * QP; idx += 256) {
        int hwl = idx / QP;
        int q   = idx - hwl * QP;
        size_t goff = (size_t)(hw0 + hwl) * (KD / 2) + q;
        gh[goff] = s_h[hwl * SROW + q];
        gl[goff] = s_l[hwl * SROW + q];
    }
}

// ---------------------------------------------------------------------------
// Kernel C: mma.sync bf16 split GEMM (validated R5 body).
// Grid swapped: x = m-tiles (2), y = n-tiles (64) so concurrent CTAs share
// B tiles in L2 (halves B DRAM traffic).
// ---------------------------------------------------------------------------
__global__ void __launch_bounds__(256, 2)
gemm_mma_kernel(float* __restrict__ out)
{
    extern __shared__ char smem[];
    const uint32_t sb = smem_u32(smem);
    const int tid = threadIdx.x;
    const int wid = tid >> 5, lane = tid & 31;
    const int warp_m = wid & 3;
    const int warp_n = wid >> 2;
    const int m0 = blockIdx.x * BM;      // swapped
    const int n0 = blockIdx.y * BNT;     // swapped
    const int b  = blockIdx.z;

    const __nv_bfloat16* Ah = g_wh + (size_t)m0 * KD;
    const __nv_bfloat16* Al = g_wl + (size_t)m0 * KD;
    const __nv_bfloat16* Bh = g_colh + ((size_t)(b * HW + n0)) * KD;
    const __nv_bfloat16* Bl = g_coll + ((size_t)(b * HW + n0)) * KD;

    const int arow0 = tid >> 2,         acs0 = (tid & 3);
    const int arow1 = (tid + 256) >> 2, acs1 = (tid & 3);
    const int brow = tid >> 2, bcs = (tid & 3);

    float c[2][4][4];
    #pragma unroll
    for (int i = 0; i < 2; i++)
        #pragma unroll
        for (int j = 0; j < 4; j++)
            #pragma unroll
            for (int q = 0; q < 4; q++) c[i][j][q] = 0.f;

    {
        uint32_t st = sb;
        cp16(st + 0 * T_A + arow0 * ROWB + acs0 * 16, Ah + (size_t)arow0 * KD + acs0 * 8);
        cp16(st + 0 * T_A + arow1 * ROWB + acs1 * 16, Ah + (size_t)arow1 * KD + acs1 * 8);
        cp16(st + 1 * T_A + arow0 * ROWB + acs0 * 16, Al + (size_t)arow0 * KD + acs0 * 8);
        cp16(st + 1 * T_A + arow1 * ROWB + acs1 * 16, Al + (size_t)arow1 * KD + acs1 * 8);
        cp16(st + 2 * T_A + brow * ROWB + bcs * 16,   Bh + (size_t)brow * KD + bcs * 8);
        cp16(st + 2 * T_A + T_B + brow * ROWB + bcs * 16, Bl + (size_t)brow * KD + bcs * 8);
        CP_COMMIT();
    }

    for (int ch = 0; ch < NCH; ch++) {
        const int cur = ch & 1;
        if (ch + 1 < NCH) {
            const int k0 = (ch + 1) * BK;
            uint32_t st = sb + (cur ^ 1) * STAGE_B;
            cp16(st + 0 * T_A + arow0 * ROWB + acs0 * 16, Ah + (size_t)arow0 * KD + k0 + acs0 * 8);
            cp16(st + 0 * T_A + arow1 * ROWB + acs1 * 16, Ah + (size_t)arow1 * KD + k0 + acs1 * 8);
            cp16(st + 1 * T_A + arow0 * ROWB + acs0 * 16, Al + (size_t)arow0 * KD + k0 + acs0 * 8);
            cp16(st + 1 * T_A + arow1 * ROWB + acs1 * 16, Al + (size_t)arow1 * KD + k0 + acs1 * 8);
            cp16(st + 2 * T_A + brow * ROWB + bcs * 16,   Bh + (size_t)brow * KD + k0 + bcs * 8);
            cp16(st + 2 * T_A + T_B + brow * ROWB + bcs * 16, Bl + (size_t)brow * KD + k0 + bcs * 8);
            CP_COMMIT();
            CP_WAIT(1);
        } else {
            CP_WAIT(0);
        }
        __syncthreads();

        const uint32_t st = sb + cur * STAGE_B;
        #pragma unroll
        for (int ks = 0; ks < 2; ks++) {
            uint32_t a_off = (uint32_t)((warp_m * 32 + (lane & 15)) * ROWB
                                        + ks * 32 + ((lane >> 4) << 4));
            uint32_t ah[2][4], al[2][4];
            #pragma unroll
            for (int mf = 0; mf < 2; mf++) {
                ldm_x4(ah[mf], st + 0 * T_A + a_off + mf * 16 * ROWB);
                ldm_x4(al[mf], st + 1 * T_A + a_off + mf * 16 * ROWB);
            }
            uint32_t b_off = (uint32_t)((warp_n * 32 + (lane & 7) + ((lane >> 4) << 3)) * ROWB
                                        + ks * 32 + (((lane >> 3) & 1) << 4));
            uint32_t bh[4][2], bl[4][2];
            #pragma unroll
            for (int nfp = 0; nfp < 2; nfp++) {
                uint32_t r[4];
                ldm_x4(r, st + 2 * T_A + b_off + nfp * 16 * ROWB);
                bh[nfp * 2][0] = r[0]; bh[nfp * 2][1] = r[1];
                bh[nfp * 2 + 1][0] = r[2]; bh[nfp * 2 + 1][1] = r[3];
                ldm_x4(r, st + 2 * T_A + T_B + b_off + nfp * 16 * ROWB);
                bl[nfp * 2][0] = r[0]; bl[nfp * 2][1] = r[1];
                bl[nfp * 2 + 1][0] = r[2]; bl[nfp * 2 + 1][1] = r[3];
            }
            #pragma unroll
            for (int mf = 0; mf < 2; mf++)
                #pragma unroll
                for (int nf = 0; nf < 4; nf++) {
                    mma_bf16(c[mf][nf], ah[mf], bh[nf]);
                    mma_bf16(c[mf][nf], ah[mf], bl[nf]);
                    mma_bf16(c[mf][nf], al[mf], bh[nf]);
                }
        }
        __syncthreads();
    }

    #pragma unroll
    for (int mf = 0; mf < 2; mf++)
        #pragma unroll
        for (int nf = 0; nf < 4; nf++) {
            int row = m0 + warp_m * 32 + mf * 16 + (lane >> 2);
            int col = n0 + warp_n * 32 + nf * 8 + 2 * (lane & 3);
            float* op0 = out + ((size_t)(b * ON + row)) * HW + col;
            float* op1 = out + ((size_t)(b * ON + row + 8)) * HW + col;
            *(float2*)op0 = make_float2(c[mf][nf][0], c[mf][nf][1]);
            *(float2*)op1 = make_float2(c[mf][nf][2], c[mf][nf][3]);
        }
}

// ---------------------------------------------------------------------------
// GroupNorm stats + normalize (validated)
// ---------------------------------------------------------------------------
__global__ void gn_stats_kernel(const float* __restrict__ y)
{
    const int bg = blockIdx.x;
    const float* p = y + (size_t)bg * GRP_ELEMS;
    float s = 0.f, ss = 0.f;
    for (int i = threadIdx.x * 4; i < GRP_ELEMS; i += blockDim.x * 4) {
        float4 v = *(const float4*)(p + i);
        s  += v.x + v.y + v.z + v.w;
        ss += v.x * v.x + v.y * v.y + v.z * v.z + v.w * v.w;
    }
    #pragma unroll
    for (int off = 16; off > 0; off >>= 1) {
        s  += __shfl_down_sync(0xffffffffu, s,  off);
        ss += __shfl_down_sync(0xffffffffu, ss, off);
    }
    __shared__ float sh_s[8], sh_ss[8];
    int wid = threadIdx.x >> 5, lid = threadIdx.x & 31;
    if (lid == 0) { sh_s[wid] = s; sh_ss[wid] = ss; }
    __syncthreads();
    if (wid == 0) {
        s  = (lid < 8) ? sh_s[lid]  : 0.f;
        ss = (lid < 8) ? sh_ss[lid] : 0.f;
        #pragma unroll
        for (int off = 4; off > 0; off >>= 1) {
            s  += __shfl_down_sync(0xffffffffu, s,  off);
            ss += __shfl_down_sync(0xffffffffu, ss, off);
        }
        if (lid == 0) {
            float mu  = s * (1.f / GRP_ELEMS);
            float var = ss * (1.f / GRP_ELEMS) - mu * mu;
            g_mu[bg]   = mu;
            g_rstd[bg] = rsqrtf(var + EPS);
        }
    }
}

__global__ void gn_norm_kernel(float* __restrict__ y,
                               const float* __restrict__ gamma,
                               const float* __restrict__ beta)
{
    int idx = blockIdx.x * blockDim.x + threadIdx.x;
    int bg = idx >> 13;
    int c  = (idx >> 10) & 255;
    float mu = g_mu[bg];
    float r  = g_rstd[bg];
    float a  = r * gamma[c];
    float bb = beta[c] - mu * a;
    float4 v = *(float4*)(y + (size_t)idx * 4);
    v.x = fmaxf(fmaf(v.x, a, bb), 0.f);
    v.y = fmaxf(fmaf(v.y, a, bb), 0.f);
    v.z = fmaxf(fmaf(v.z, a, bb), 0.f);
    v.w = fmaxf(fmaf(v.w, a, bb), 0.f);
    *(float4*)(y + (size_t)idx * 4) = v;
}

// ---------------------------------------------------------------------------
// Launcher
// ---------------------------------------------------------------------------
extern "C" void kernel_launch(void* const* d_in, const int* in_sizes, int n_in,
                              void* d_out, int out_size)
{
    const float* x        = (const float*)d_in[0];
    const float* x_off    = (const float*)d_in[1];
    const float* w_offset = (const float*)d_in[2];
    const float* w_deform = (const float*)d_in[3];
    const float* gamma    = (const float*)d_in[4];
    const float* beta     = (const float*)d_in[5];
    float* out = (float*)d_out;

    cudaFuncSetAttribute(gemm_mma_kernel,
                         cudaFuncAttributeMaxDynamicSharedMemorySize,
                         SMEM_TOTAL);

    // 1) weight split
    wsplit_kernel<<<(ON * KD) / 256, 256>>>(w_deform);
    // 2) deformable im2col v3 (SMEM-staged transpose)
    {
        dim3 grid(HW / V3HW, DGN, BN);       // (256, 4, 8)
        im2col3_kernel<<<grid, 256>>>(x, x_off, w_offset);
    }
    // 3) tensor-core GEMM (m-tiles fastest for B L2 reuse)
    {
        dim3 grid(ON / BM, HW / BNT, BN);    // (2, 64, 8)
        gemm_mma_kernel<<<grid, 256, SMEM_TOTAL>>>(out);
    }
    // 4) GroupNorm
    gn_stats_kernel<<<BN * GN_GROUPS, 256>>>(out);
    gn_norm_kernel<<<(BN * ON * HW / 4) / 256, 256>>>(out, gamma, beta);
}